// round 11
// baseline (speedup 1.0000x reference)
#include <cuda_runtime.h>
#include <cuda_bf16.h>
#include <cstdint>

#define B_   64
#define T_   4096
#define DIM_ 256
#define NF_  32
#define KS_  31
#define PAD_ 15
#define NEG_ (-1e30f)
#define BT_  (B_ * T_)

// ---------------- scratch (device globals; no allocations) ----------------
__device__ float g_q[B_ * DIM_];                     // 64 KB
__device__ __nv_bfloat16 g_Fh[(size_t)BT_ * NF_];    // 16 MB conv features (bf16)
__device__ float g_S[BT_];                           // raw masked scores
__device__ unsigned char g_mask[BT_];                // normalized mask
__device__ float g_partial[8 * B_ * DIM_];           // context partials
__device__ float g_align_scratch[BT_];
__device__ float g_att_scratch[B_ * DIM_];
__device__ int   g_det[2];

// ---------------- K0: mask dtype detection + normalization ----------------
__global__ void k_reset() { g_det[0] = 0; g_det[1] = 0; }

__global__ void k_detect(const unsigned int* __restrict__ mw) {
    int i = (blockIdx.x * 256 + threadIdx.x) * 4;
#pragma unroll
    for (int j = 0; j < 4; ++j) {
        unsigned v = mw[i + j];
        if (v == 0x3f800000u)      atomicOr(&g_det[1], 1);   // float 1.0
        else if (v > 1u)           atomicOr(&g_det[0], 1);   // packed bytes
    }
}

__global__ void k_mconv(const void* __restrict__ m) {
    int i = blockIdx.x * 256 + threadIdx.x;
    if (i >= BT_) return;
    int isf32 = g_det[1], isu8 = g_det[0];
    unsigned char r;
    if (isf32)      r = (((const float*)m)[i] != 0.0f);
    else if (isu8)  r = (((const unsigned char*)m)[i] != 0);
    else            r = (((const int*)m)[i] != 0);
    g_mask[i] = r;
}

// ---------------- K1: q = query @ Wq^T  (coalesced, warp-per-output) ------
__global__ void k_qproj(const float* __restrict__ query, const float* __restrict__ Wq) {
    __shared__ float qs[DIM_];
    const int b = blockIdx.x, tid = threadIdx.x;
    const int w = tid >> 5, lane = tid & 31;
    qs[tid] = query[b * DIM_ + tid];
    __syncthreads();
#pragma unroll 4
    for (int j = 0; j < 32; ++j) {
        const int d = w + j * 8;
        const float* wr = Wq + (size_t)d * DIM_;
        float a = 0.0f;
#pragma unroll
        for (int e = 0; e < 8; ++e)
            a = fmaf(wr[lane + 32 * e], qs[lane + 32 * e], a);
#pragma unroll
        for (int o = 16; o > 0; o >>= 1)
            a += __shfl_xor_sync(0xffffffffu, a, o);
        if (lane == 0) g_q[b * DIM_ + d] = a;
    }
}

// ---------------- K2: conv -> g_Fh (bf16). taps in regs, sliding window ---
__global__ void __launch_bounds__(256) k_conv(const float* __restrict__ pa,
                                              const float* __restrict__ cw) {
    __shared__ float pa_sh[160];             // 128 + 31 (one extra pad slot)
    __shared__ float cw_sh[NF_ * KS_];
    const int b = blockIdx.y, t0 = blockIdx.x * 128;
    const int tid = threadIdx.x, wid = tid >> 5, lane = tid & 31;
    for (int i = tid; i < 160; i += 256) {
        int t = t0 + i - PAD_;
        pa_sh[i] = (t >= 0 && t < T_) ? pa[b * T_ + t] : 0.0f;
    }
    for (int i = tid; i < NF_ * KS_; i += 256) cw_sh[i] = cw[i];
    __syncthreads();

    float cr[KS_];
#pragma unroll
    for (int k = 0; k < KS_; ++k) cr[k] = cw_sh[lane * KS_ + k];   // conflict-free (31 stride)
    float wv[KS_];
#pragma unroll
    for (int k = 0; k < KS_; ++k) wv[k] = pa_sh[wid * 16 + k];     // broadcast

    __nv_bfloat16* dst = g_Fh + ((size_t)(b * T_ + t0 + wid * 16)) * NF_ + lane;
#pragma unroll
    for (int i = 0; i < 16; ++i) {
        float a = 0.0f;
#pragma unroll
        for (int k = 0; k < KS_; ++k) a = fmaf(wv[k], cr[k], a);
        dst[(size_t)i * NF_] = __float2bfloat16(a);
#pragma unroll
        for (int k = 0; k < KS_ - 1; ++k) wv[k] = wv[k + 1];       // reg-renamed
        wv[KS_ - 1] = pa_sh[wid * 16 + i + KS_];                   // max idx 157 < 160
    }
}

// ---------------- K3: fused score kernel (bf16 tensor-core loc GEMM) ------
#define FP 40   // bf16 smem pitch: (row*20 + tig) mod 32 distinct -> conflict-free

__device__ __forceinline__ float score_term(float c, float kq, float v) {
    // v * tanh(c + kq),  tanh(x) = 1 - 2/(e^{2x}+1)
    float x = c + kq;
    float e = __expf(x + x);
    return v - __fdividef(v + v, e + 1.0f);
}

__global__ void __launch_bounds__(256)
k_score(const float* __restrict__ keys, const float* __restrict__ Wloc,
        const float* __restrict__ vw, const float* __restrict__ vb) {
    __shared__ __align__(16) __nv_bfloat16 F_sh[128 * FP];    // 10.0 KB
    __shared__ __align__(16) __nv_bfloat16 W_sh[DIM_ * FP];   // 20.0 KB
    __shared__ float q_sh[DIM_], v_sh[DIM_];

    const int b = blockIdx.y, t0 = blockIdx.x * 128;
    const int tid = threadIdx.x, w = tid >> 5, lane = tid & 31;
    const int g = lane >> 2, tg = lane & 3;

    // stage Wloc -> bf16 [d][f] (row-major == col-major k16n8 B operand)
    for (int idx = tid; idx < DIM_ * NF_; idx += 256)
        W_sh[(idx >> 5) * FP + (idx & 31)] = __float2bfloat16(Wloc[idx]);
    q_sh[tid] = g_q[b * DIM_ + tid];
    v_sh[tid] = vw[tid];
    // stage F tile (128 x 32 bf16) as u32
    {
        const uint32_t* src = (const uint32_t*)(g_Fh + (size_t)(b * T_ + t0) * NF_);
        uint32_t* dstF = (uint32_t*)F_sh;
        for (int idx = tid; idx < 128 * 16; idx += 256) {
            int row = idx >> 4, col = idx & 15;
            dstF[row * (FP / 2) + col] = src[idx];
        }
    }
    const float vb0 = vb[0];
    __syncthreads();

    // A fragments (m16k16, 2 k-steps) for this warp's 16 t-rows
    const __nv_bfloat16* Fb = F_sh + (w * 16) * FP;
    uint32_t a[2][4];
#pragma unroll
    for (int ks = 0; ks < 2; ++ks) {
        const int f0 = ks * 16 + 2 * tg;
        a[ks][0] = *(const uint32_t*)(Fb + g * FP + f0);
        a[ks][1] = *(const uint32_t*)(Fb + (g + 8) * FP + f0);
        a[ks][2] = *(const uint32_t*)(Fb + g * FP + f0 + 8);
        a[ks][3] = *(const uint32_t*)(Fb + (g + 8) * FP + f0 + 8);
    }

    const size_t row0 = (size_t)(b * T_ + t0 + w * 16 + g) * DIM_;
    const size_t row8 = row0 + 8 * DIM_;
    float sc0 = 0.0f, sc1 = 0.0f;

#pragma unroll 2
    for (int nt = 0; nt < 32; ++nt) {
        const int n0 = nt * 8;
        const int d  = n0 + 2 * tg;
        const __nv_bfloat16* Wb = W_sh + (n0 + g) * FP + 2 * tg;
        const uint32_t b00 = *(const uint32_t*)(Wb);
        const uint32_t b01 = *(const uint32_t*)(Wb + 8);
        const uint32_t b10 = *(const uint32_t*)(Wb + 16);
        const uint32_t b11 = *(const uint32_t*)(Wb + 24);
        // prefetch keys + per-d constants while MMA runs
        const float2 k0 = *(const float2*)(keys + row0 + d);
        const float2 k1 = *(const float2*)(keys + row8 + d);
        const float2 q2 = *(const float2*)&q_sh[d];
        const float2 v2 = *(const float2*)&v_sh[d];

        float c0 = 0.f, c1 = 0.f, c2 = 0.f, c3 = 0.f;
        asm volatile(
            "mma.sync.aligned.m16n8k16.row.col.f32.bf16.bf16.f32 "
            "{%0,%1,%2,%3}, {%4,%5,%6,%7}, {%8,%9}, {%0,%1,%2,%3};"
            : "+f"(c0), "+f"(c1), "+f"(c2), "+f"(c3)
            : "r"(a[0][0]), "r"(a[0][1]), "r"(a[0][2]), "r"(a[0][3]),
              "r"(b00), "r"(b01));
        asm volatile(
            "mma.sync.aligned.m16n8k16.row.col.f32.bf16.bf16.f32 "
            "{%0,%1,%2,%3}, {%4,%5,%6,%7}, {%8,%9}, {%0,%1,%2,%3};"
            : "+f"(c0), "+f"(c1), "+f"(c2), "+f"(c3)
            : "r"(a[1][0]), "r"(a[1][1]), "r"(a[1][2]), "r"(a[1][3]),
              "r"(b10), "r"(b11));

        sc0 += score_term(c0, k0.x + q2.x, v2.x) + score_term(c1, k0.y + q2.y, v2.y);
        sc1 += score_term(c2, k1.x + q2.x, v2.x) + score_term(c3, k1.y + q2.y, v2.y);
    }

    // reduce over the 4 lanes sharing a t-row (each covered d%8 in {2tg,2tg+1})
    sc0 += __shfl_xor_sync(0xffffffffu, sc0, 1);
    sc0 += __shfl_xor_sync(0xffffffffu, sc0, 2);
    sc1 += __shfl_xor_sync(0xffffffffu, sc1, 1);
    sc1 += __shfl_xor_sync(0xffffffffu, sc1, 2);
    if (tg == 0) {
        const int t = t0 + w * 16 + g;
        float s0 = sc0 + vb0; if (g_mask[b * T_ + t])     s0 = NEG_;
        float s1 = sc1 + vb0; if (g_mask[b * T_ + t + 8]) s1 = NEG_;
        g_S[b * T_ + t]     = s0;
        g_S[b * T_ + t + 8] = s1;
    }
}

// ---------------- K4: softmax per row ----------------
__global__ void k_softmax(float* __restrict__ align_out) {
    const int b = blockIdx.x, tid = threadIdx.x;   // 512 threads
    __shared__ float sha[16], shb[16];
    float v[8];
    float mx = -3.4e38f;
#pragma unroll
    for (int i = 0; i < 8; ++i) {
        v[i] = g_S[b * T_ + tid + i * 512];
        mx = fmaxf(mx, v[i]);
    }
#pragma unroll
    for (int o = 16; o > 0; o >>= 1) mx = fmaxf(mx, __shfl_xor_sync(0xffffffffu, mx, o));
    if ((tid & 31) == 0) sha[tid >> 5] = mx;
    __syncthreads();
    if (tid < 32) {
        float t = (tid < 16) ? sha[tid] : -3.4e38f;
#pragma unroll
        for (int o = 8; o > 0; o >>= 1) t = fmaxf(t, __shfl_xor_sync(0xffffffffu, t, o));
        if (tid == 0) sha[0] = t;
    }
    __syncthreads();
    mx = sha[0];
    float sum = 0.0f;
#pragma unroll
    for (int i = 0; i < 8; ++i) { v[i] = __expf(v[i] - mx); sum += v[i]; }
#pragma unroll
    for (int o = 16; o > 0; o >>= 1) sum += __shfl_xor_sync(0xffffffffu, sum, o);
    if ((tid & 31) == 0) shb[tid >> 5] = sum;
    __syncthreads();
    if (tid < 32) {
        float t = (tid < 16) ? shb[tid] : 0.0f;
#pragma unroll
        for (int o = 8; o > 0; o >>= 1) t += __shfl_xor_sync(0xffffffffu, t, o);
        if (tid == 0) shb[0] = t;
    }
    __syncthreads();
    const float inv = 1.0f / shb[0];
#pragma unroll
    for (int i = 0; i < 8; ++i)
        align_out[b * T_ + tid + i * 512] = v[i] * inv;
}

// ---------------- K5: context partials (8 splits) + K6: reduce ----------------
__global__ void __launch_bounds__(256) k_context(const float* __restrict__ values,
                                                 const float* __restrict__ align) {
    __shared__ float al[512];
    const int b = blockIdx.y, sp = blockIdx.x, tid = threadIdx.x;
    const int tbase = sp * 512;
    al[tid]       = align[b * T_ + tbase + tid];
    al[tid + 256] = align[b * T_ + tbase + tid + 256];
    __syncthreads();
    const float* vp = values + ((size_t)(b * T_ + tbase)) * DIM_ + tid;
    float acc = 0.0f;
#pragma unroll 16
    for (int t = 0; t < 512; ++t)
        acc = fmaf(al[t], vp[(size_t)t * DIM_], acc);
    g_partial[(sp * B_ + b) * DIM_ + tid] = acc;
}

__global__ void k_reduce(float* __restrict__ att_out) {
    const int b = blockIdx.x, d = threadIdx.x;
    float s = 0.0f;
#pragma unroll
    for (int sp = 0; sp < 8; ++sp) s += g_partial[(sp * B_ + b) * DIM_ + d];
    att_out[b * DIM_ + d] = s;
}

// ---------------- launch ----------------
extern "C" void kernel_launch(void* const* d_in, const int* in_sizes, int n_in,
                              void* d_out, int out_size) {
    const float* query  = (const float*)d_in[0];
    const float* keys   = (const float*)d_in[1];
    const float* values = (const float*)d_in[2];
    const float* pa     = (const float*)d_in[3];
    const void*  mask   = d_in[4];
    const float* Wq     = (const float*)d_in[5];
    const float* cw     = (const float*)d_in[6];
    const float* Wloc   = (const float*)d_in[7];
    const float* vw     = (const float*)d_in[8];
    const float* vb     = (const float*)d_in[9];

    float* out = (float*)d_out;
    float *att_ptr, *align_ptr;
    if (out_size >= B_ * DIM_ + BT_) {
        att_ptr = out;
        align_ptr = out + B_ * DIM_;
    } else if (out_size == BT_) {
        float* p; cudaGetSymbolAddress((void**)&p, g_att_scratch);
        att_ptr = p; align_ptr = out;
    } else {
        float* p; cudaGetSymbolAddress((void**)&p, g_align_scratch);
        att_ptr = out; align_ptr = p;
    }

    k_reset<<<1, 1>>>();
    k_detect<<<64, 256>>>((const unsigned int*)mask);
    k_mconv<<<BT_ / 256, 256>>>(mask);
    k_qproj<<<B_, 256>>>(query, Wq);
    k_conv<<<dim3(T_ / 128, B_), 256>>>(pa, cw);
    k_score<<<dim3(T_ / 128, B_), 256>>>(keys, Wloc, vw, vb);
    k_softmax<<<B_, 512>>>(align_ptr);
    k_context<<<dim3(8, B_), 256>>>(values, align_ptr);
    k_reduce<<<B_, DIM_>>>(att_ptr);
}

// round 12
// speedup vs baseline: 1.0002x; 1.0002x over previous
#include <cuda_runtime.h>
#include <cuda_bf16.h>
#include <cstdint>

#define B_   64
#define T_   4096
#define DIM_ 256
#define NF_  32
#define KS_  31
#define PAD_ 15
#define NEG_ (-1e30f)
#define BT_  (B_ * T_)

// ---------------- scratch (device globals; no allocations) ----------------
__device__ float g_q[B_ * DIM_];                     // 64 KB
__device__ __nv_bfloat16 g_Fh[(size_t)BT_ * NF_];    // 16 MB conv features (bf16)
__device__ float g_S[BT_];                           // raw masked scores
__device__ unsigned char g_mask[BT_];                // normalized mask
__device__ float g_partial[8 * B_ * DIM_];           // context partials
__device__ float g_align_scratch[BT_];
__device__ float g_att_scratch[B_ * DIM_];
__device__ int   g_det[2];

// ---------------- K0: mask dtype detection + normalization ----------------
__global__ void k_reset() { g_det[0] = 0; g_det[1] = 0; }

__global__ void k_detect(const unsigned int* __restrict__ mw) {
    int i = (blockIdx.x * 256 + threadIdx.x) * 4;
#pragma unroll
    for (int j = 0; j < 4; ++j) {
        unsigned v = mw[i + j];
        if (v == 0x3f800000u)      atomicOr(&g_det[1], 1);   // float 1.0
        else if (v > 1u)           atomicOr(&g_det[0], 1);   // packed bytes
    }
}

__global__ void k_mconv(const void* __restrict__ m) {
    int i = blockIdx.x * 256 + threadIdx.x;
    if (i >= BT_) return;
    int isf32 = g_det[1], isu8 = g_det[0];
    unsigned char r;
    if (isf32)      r = (((const float*)m)[i] != 0.0f);
    else if (isu8)  r = (((const unsigned char*)m)[i] != 0);
    else            r = (((const int*)m)[i] != 0);
    g_mask[i] = r;
}

// ---------------- K1: q = query @ Wq^T  (coalesced, warp-per-output) ------
__global__ void k_qproj(const float* __restrict__ query, const float* __restrict__ Wq) {
    __shared__ float qs[DIM_];
    const int b = blockIdx.x, tid = threadIdx.x;
    const int w = tid >> 5, lane = tid & 31;
    qs[tid] = query[b * DIM_ + tid];
    __syncthreads();
#pragma unroll 4
    for (int j = 0; j < 32; ++j) {
        const int d = w + j * 8;
        const float* wr = Wq + (size_t)d * DIM_;
        float a = 0.0f;
#pragma unroll
        for (int e = 0; e < 8; ++e)
            a = fmaf(wr[lane + 32 * e], qs[lane + 32 * e], a);
#pragma unroll
        for (int o = 16; o > 0; o >>= 1)
            a += __shfl_xor_sync(0xffffffffu, a, o);
        if (lane == 0) g_q[b * DIM_ + d] = a;
    }
}

// ---------------- K2: conv -> g_Fh (bf16). taps in regs, sliding window ---
__global__ void __launch_bounds__(256) k_conv(const float* __restrict__ pa,
                                              const float* __restrict__ cw) {
    __shared__ float pa_sh[160];             // 128 + 31 (one extra pad slot)
    __shared__ float cw_sh[NF_ * KS_];
    const int b = blockIdx.y, t0 = blockIdx.x * 128;
    const int tid = threadIdx.x, wid = tid >> 5, lane = tid & 31;
    for (int i = tid; i < 160; i += 256) {
        int t = t0 + i - PAD_;
        pa_sh[i] = (t >= 0 && t < T_) ? pa[b * T_ + t] : 0.0f;
    }
    for (int i = tid; i < NF_ * KS_; i += 256) cw_sh[i] = cw[i];
    __syncthreads();

    float cr[KS_];
#pragma unroll
    for (int k = 0; k < KS_; ++k) cr[k] = cw_sh[lane * KS_ + k];   // conflict-free (31 stride)
    float wv[KS_];
#pragma unroll
    for (int k = 0; k < KS_; ++k) wv[k] = pa_sh[wid * 16 + k];     // broadcast

    __nv_bfloat16* dst = g_Fh + ((size_t)(b * T_ + t0 + wid * 16)) * NF_ + lane;
#pragma unroll
    for (int i = 0; i < 16; ++i) {
        float a = 0.0f;
#pragma unroll
        for (int k = 0; k < KS_; ++k) a = fmaf(wv[k], cr[k], a);
        dst[(size_t)i * NF_] = __float2bfloat16(a);
#pragma unroll
        for (int k = 0; k < KS_ - 1; ++k) wv[k] = wv[k + 1];       // reg-renamed
        wv[KS_ - 1] = pa_sh[wid * 16 + i + KS_];                   // max idx 157 < 160
    }
}

// ---------------- K3: fused score kernel (bf16 tensor-core loc GEMM) ------
#define FP 40   // bf16 smem pitch: (row*20 + tig) mod 32 distinct -> conflict-free

__device__ __forceinline__ float score_term(float c, float kq, float v) {
    // v * tanh(c + kq),  tanh(x) = 1 - 2/(e^{2x}+1)
    float x = c + kq;
    float e = __expf(x + x);
    return v - __fdividef(v + v, e + 1.0f);
}

__global__ void __launch_bounds__(256)
k_score(const float* __restrict__ keys, const float* __restrict__ Wloc,
        const float* __restrict__ vw, const float* __restrict__ vb) {
    __shared__ __align__(16) __nv_bfloat16 F_sh[128 * FP];    // 10.0 KB
    __shared__ __align__(16) __nv_bfloat16 W_sh[DIM_ * FP];   // 20.0 KB
    __shared__ float q_sh[DIM_], v_sh[DIM_];

    const int b = blockIdx.y, t0 = blockIdx.x * 128;
    const int tid = threadIdx.x, w = tid >> 5, lane = tid & 31;
    const int g = lane >> 2, tg = lane & 3;

    // stage Wloc -> bf16 [d][f] (row-major == col-major k16n8 B operand)
    for (int idx = tid; idx < DIM_ * NF_; idx += 256)
        W_sh[(idx >> 5) * FP + (idx & 31)] = __float2bfloat16(Wloc[idx]);
    q_sh[tid] = g_q[b * DIM_ + tid];
    v_sh[tid] = vw[tid];
    // stage F tile (128 x 32 bf16) as u32
    {
        const uint32_t* src = (const uint32_t*)(g_Fh + (size_t)(b * T_ + t0) * NF_);
        uint32_t* dstF = (uint32_t*)F_sh;
        for (int idx = tid; idx < 128 * 16; idx += 256) {
            int row = idx >> 4, col = idx & 15;
            dstF[row * (FP / 2) + col] = src[idx];
        }
    }
    const float vb0 = vb[0];
    __syncthreads();

    // A fragments (m16k16, 2 k-steps) for this warp's 16 t-rows
    const __nv_bfloat16* Fb = F_sh + (w * 16) * FP;
    uint32_t a[2][4];
#pragma unroll
    for (int ks = 0; ks < 2; ++ks) {
        const int f0 = ks * 16 + 2 * tg;
        a[ks][0] = *(const uint32_t*)(Fb + g * FP + f0);
        a[ks][1] = *(const uint32_t*)(Fb + (g + 8) * FP + f0);
        a[ks][2] = *(const uint32_t*)(Fb + g * FP + f0 + 8);
        a[ks][3] = *(const uint32_t*)(Fb + (g + 8) * FP + f0 + 8);
    }

    const size_t row0 = (size_t)(b * T_ + t0 + w * 16 + g) * DIM_;
    const size_t row8 = row0 + 8 * DIM_;
    float sc0 = 0.0f, sc1 = 0.0f;

#pragma unroll 2
    for (int nt = 0; nt < 32; ++nt) {
        const int n0 = nt * 8;
        const int d  = n0 + 2 * tg;
        const __nv_bfloat16* Wb = W_sh + (n0 + g) * FP + 2 * tg;
        const uint32_t b00 = *(const uint32_t*)(Wb);
        const uint32_t b01 = *(const uint32_t*)(Wb + 8);
        const uint32_t b10 = *(const uint32_t*)(Wb + 16);
        const uint32_t b11 = *(const uint32_t*)(Wb + 24);
        // prefetch keys + per-d constants while MMA runs
        const float2 k0 = *(const float2*)(keys + row0 + d);
        const float2 k1 = *(const float2*)(keys + row8 + d);
        const float2 q2 = *(const float2*)&q_sh[d];
        const float2 v2 = *(const float2*)&v_sh[d];

        float c0 = 0.f, c1 = 0.f, c2 = 0.f, c3 = 0.f;
        asm volatile(
            "mma.sync.aligned.m16n8k16.row.col.f32.bf16.bf16.f32 "
            "{%0,%1,%2,%3}, {%4,%5,%6,%7}, {%8,%9}, {%0,%1,%2,%3};"
            : "+f"(c0), "+f"(c1), "+f"(c2), "+f"(c3)
            : "r"(a[0][0]), "r"(a[0][1]), "r"(a[0][2]), "r"(a[0][3]),
              "r"(b00), "r"(b01));
        asm volatile(
            "mma.sync.aligned.m16n8k16.row.col.f32.bf16.bf16.f32 "
            "{%0,%1,%2,%3}, {%4,%5,%6,%7}, {%8,%9}, {%0,%1,%2,%3};"
            : "+f"(c0), "+f"(c1), "+f"(c2), "+f"(c3)
            : "r"(a[1][0]), "r"(a[1][1]), "r"(a[1][2]), "r"(a[1][3]),
              "r"(b10), "r"(b11));

        sc0 += score_term(c0, k0.x + q2.x, v2.x) + score_term(c1, k0.y + q2.y, v2.y);
        sc1 += score_term(c2, k1.x + q2.x, v2.x) + score_term(c3, k1.y + q2.y, v2.y);
    }

    // reduce over the 4 lanes sharing a t-row (each covered d%8 in {2tg,2tg+1})
    sc0 += __shfl_xor_sync(0xffffffffu, sc0, 1);
    sc0 += __shfl_xor_sync(0xffffffffu, sc0, 2);
    sc1 += __shfl_xor_sync(0xffffffffu, sc1, 1);
    sc1 += __shfl_xor_sync(0xffffffffu, sc1, 2);
    if (tg == 0) {
        const int t = t0 + w * 16 + g;
        float s0 = sc0 + vb0; if (g_mask[b * T_ + t])     s0 = NEG_;
        float s1 = sc1 + vb0; if (g_mask[b * T_ + t + 8]) s1 = NEG_;
        g_S[b * T_ + t]     = s0;
        g_S[b * T_ + t + 8] = s1;
    }
}

// ---------------- K4: softmax per row ----------------
__global__ void k_softmax(float* __restrict__ align_out) {
    const int b = blockIdx.x, tid = threadIdx.x;   // 512 threads
    __shared__ float sha[16], shb[16];
    float v[8];
    float mx = -3.4e38f;
#pragma unroll
    for (int i = 0; i < 8; ++i) {
        v[i] = g_S[b * T_ + tid + i * 512];
        mx = fmaxf(mx, v[i]);
    }
#pragma unroll
    for (int o = 16; o > 0; o >>= 1) mx = fmaxf(mx, __shfl_xor_sync(0xffffffffu, mx, o));
    if ((tid & 31) == 0) sha[tid >> 5] = mx;
    __syncthreads();
    if (tid < 32) {
        float t = (tid < 16) ? sha[tid] : -3.4e38f;
#pragma unroll
        for (int o = 8; o > 0; o >>= 1) t = fmaxf(t, __shfl_xor_sync(0xffffffffu, t, o));
        if (tid == 0) sha[0] = t;
    }
    __syncthreads();
    mx = sha[0];
    float sum = 0.0f;
#pragma unroll
    for (int i = 0; i < 8; ++i) { v[i] = __expf(v[i] - mx); sum += v[i]; }
#pragma unroll
    for (int o = 16; o > 0; o >>= 1) sum += __shfl_xor_sync(0xffffffffu, sum, o);
    if ((tid & 31) == 0) shb[tid >> 5] = sum;
    __syncthreads();
    if (tid < 32) {
        float t = (tid < 16) ? shb[tid] : 0.0f;
#pragma unroll
        for (int o = 8; o > 0; o >>= 1) t += __shfl_xor_sync(0xffffffffu, t, o);
        if (tid == 0) shb[0] = t;
    }
    __syncthreads();
    const float inv = 1.0f / shb[0];
#pragma unroll
    for (int i = 0; i < 8; ++i)
        align_out[b * T_ + tid + i * 512] = v[i] * inv;
}

// ---------------- K5: context partials (8 splits) + K6: reduce ----------------
__global__ void __launch_bounds__(256) k_context(const float* __restrict__ values,
                                                 const float* __restrict__ align) {
    __shared__ float al[512];
    const int b = blockIdx.y, sp = blockIdx.x, tid = threadIdx.x;
    const int tbase = sp * 512;
    al[tid]       = align[b * T_ + tbase + tid];
    al[tid + 256] = align[b * T_ + tbase + tid + 256];
    __syncthreads();
    const float* vp = values + ((size_t)(b * T_ + tbase)) * DIM_ + tid;
    float acc = 0.0f;
#pragma unroll 16
    for (int t = 0; t < 512; ++t)
        acc = fmaf(al[t], vp[(size_t)t * DIM_], acc);
    g_partial[(sp * B_ + b) * DIM_ + tid] = acc;
}

__global__ void k_reduce(float* __restrict__ att_out) {
    const int b = blockIdx.x, d = threadIdx.x;
    float s = 0.0f;
#pragma unroll
    for (int sp = 0; sp < 8; ++sp) s += g_partial[(sp * B_ + b) * DIM_ + d];
    att_out[b * DIM_ + d] = s;
}

// ---------------- launch ----------------
extern "C" void kernel_launch(void* const* d_in, const int* in_sizes, int n_in,
                              void* d_out, int out_size) {
    const float* query  = (const float*)d_in[0];
    const float* keys   = (const float*)d_in[1];
    const float* values = (const float*)d_in[2];
    const float* pa     = (const float*)d_in[3];
    const void*  mask   = d_in[4];
    const float* Wq     = (const float*)d_in[5];
    const float* cw     = (const float*)d_in[6];
    const float* Wloc   = (const float*)d_in[7];
    const float* vw     = (const float*)d_in[8];
    const float* vb     = (const float*)d_in[9];

    float* out = (float*)d_out;
    float *att_ptr, *align_ptr;
    if (out_size >= B_ * DIM_ + BT_) {
        att_ptr = out;
        align_ptr = out + B_ * DIM_;
    } else if (out_size == BT_) {
        float* p; cudaGetSymbolAddress((void**)&p, g_att_scratch);
        att_ptr = p; align_ptr = out;
    } else {
        float* p; cudaGetSymbolAddress((void**)&p, g_align_scratch);
        att_ptr = out; align_ptr = p;
    }

    k_reset<<<1, 1>>>();
    k_detect<<<64, 256>>>((const unsigned int*)mask);
    k_mconv<<<BT_ / 256, 256>>>(mask);
    k_qproj<<<B_, 256>>>(query, Wq);
    k_conv<<<dim3(T_ / 128, B_), 256>>>(pa, cw);
    k_score<<<dim3(T_ / 128, B_), 256>>>(keys, Wloc, vw, vb);
    k_softmax<<<B_, 512>>>(align_ptr);
    k_context<<<dim3(8, B_), 256>>>(values, align_ptr);
    k_reduce<<<B_, DIM_>>>(att_ptr);
}

// round 13
// speedup vs baseline: 1.0491x; 1.0489x over previous
#include <cuda_runtime.h>
#include <cuda_bf16.h>
#include <cstdint>

#define B_   64
#define T_   4096
#define DIM_ 256
#define NF_  32
#define KS_  31
#define PAD_ 15
#define NEG_ (-1e30f)
#define BT_  (B_ * T_)
#define NSPLIT 16

// ---------------- scratch (device globals; no allocations) ----------------
__device__ float g_q[B_ * DIM_];                     // 64 KB
__device__ __nv_bfloat16 g_Fh[(size_t)BT_ * NF_];    // 16 MB conv features (bf16)
__device__ float g_S[BT_];                           // raw masked scores
__device__ float g_partial[NSPLIT * B_ * DIM_];      // context partials
__device__ float g_align_scratch[BT_];
__device__ float g_att_scratch[B_ * DIM_];
__device__ int   g_det[2];

// ---------------- K0: mask dtype detection ----------------
__global__ void k_reset() { g_det[0] = 0; g_det[1] = 0; }

// sample first 65536 words (256KB == min possible mask buffer size)
__global__ void k_detect(const unsigned int* __restrict__ mw) {
    int i = (blockIdx.x * 256 + threadIdx.x) * 4;
#pragma unroll
    for (int j = 0; j < 4; ++j) {
        unsigned v = mw[i + j];
        if (v == 0x3f800000u)      atomicOr(&g_det[1], 1);   // float 1.0
        else if (v > 1u)           atomicOr(&g_det[0], 1);   // packed bytes
    }
}

__device__ __forceinline__ bool mask_at(const void* m, int idx, int isf, int isu8) {
    if (isf)  return ((const float*)m)[idx] != 0.0f;
    if (isu8) return ((const unsigned char*)m)[idx] != 0;
    return ((const int*)m)[idx] != 0;
}

// ---------------- K1: q = query @ Wq^T  (4-way interleaved, 128 blocks) ---
__global__ void __launch_bounds__(256) k_qproj(const float* __restrict__ query,
                                               const float* __restrict__ Wq) {
    __shared__ float qs[DIM_];
    const int b = blockIdx.y, half = blockIdx.x;
    const int tid = threadIdx.x, w = tid >> 5, lane = tid & 31;
    qs[tid] = query[b * DIM_ + tid];
    __syncthreads();
    const int dbase = half * 128 + w * 16;
#pragma unroll
    for (int it = 0; it < 4; ++it) {
        const int d0 = dbase + it * 4;
        float a0 = 0.f, a1 = 0.f, a2 = 0.f, a3 = 0.f;
        const float* r0 = Wq + (size_t)(d0 + 0) * DIM_;
        const float* r1 = Wq + (size_t)(d0 + 1) * DIM_;
        const float* r2 = Wq + (size_t)(d0 + 2) * DIM_;
        const float* r3 = Wq + (size_t)(d0 + 3) * DIM_;
#pragma unroll
        for (int e = 0; e < 8; ++e) {
            const int c = lane + 32 * e;
            const float q = qs[c];
            a0 = fmaf(r0[c], q, a0);
            a1 = fmaf(r1[c], q, a1);
            a2 = fmaf(r2[c], q, a2);
            a3 = fmaf(r3[c], q, a3);
        }
#pragma unroll
        for (int o = 16; o > 0; o >>= 1) {
            a0 += __shfl_xor_sync(0xffffffffu, a0, o);
            a1 += __shfl_xor_sync(0xffffffffu, a1, o);
            a2 += __shfl_xor_sync(0xffffffffu, a2, o);
            a3 += __shfl_xor_sync(0xffffffffu, a3, o);
        }
        if (lane == 0)
            *(float4*)&g_q[b * DIM_ + d0] = make_float4(a0, a1, a2, a3);
    }
}

// ---------------- K2: conv -> g_Fh (bf16). taps in regs, sliding window ---
__global__ void __launch_bounds__(256) k_conv(const float* __restrict__ pa,
                                              const float* __restrict__ cw) {
    __shared__ float pa_sh[160];             // 128 + 31 (one extra pad slot)
    __shared__ float cw_sh[NF_ * KS_];
    const int b = blockIdx.y, t0 = blockIdx.x * 128;
    const int tid = threadIdx.x, wid = tid >> 5, lane = tid & 31;
    for (int i = tid; i < 160; i += 256) {
        int t = t0 + i - PAD_;
        pa_sh[i] = (t >= 0 && t < T_) ? pa[b * T_ + t] : 0.0f;
    }
    for (int i = tid; i < NF_ * KS_; i += 256) cw_sh[i] = cw[i];
    __syncthreads();

    float cr[KS_];
#pragma unroll
    for (int k = 0; k < KS_; ++k) cr[k] = cw_sh[lane * KS_ + k];   // conflict-free (31 stride)
    float wv[KS_];
#pragma unroll
    for (int k = 0; k < KS_; ++k) wv[k] = pa_sh[wid * 16 + k];     // broadcast

    __nv_bfloat16* dst = g_Fh + ((size_t)(b * T_ + t0 + wid * 16)) * NF_ + lane;
#pragma unroll
    for (int i = 0; i < 16; ++i) {
        float a = 0.0f;
#pragma unroll
        for (int k = 0; k < KS_; ++k) a = fmaf(wv[k], cr[k], a);
        dst[(size_t)i * NF_] = __float2bfloat16(a);
#pragma unroll
        for (int k = 0; k < KS_ - 1; ++k) wv[k] = wv[k + 1];       // reg-renamed
        wv[KS_ - 1] = pa_sh[wid * 16 + i + KS_];                   // max idx 157 < 160
    }
}

// ---------------- K3: fused score kernel (bf16 tensor-core loc GEMM) ------
#define FP 40   // bf16 smem pitch: (row*20 + tig) mod 32 distinct -> conflict-free

__device__ __forceinline__ float score_term(float c, float kq, float v) {
    // v * tanh(c + kq),  tanh(x) = 1 - 2/(e^{2x}+1)
    float x = c + kq;
    float e = __expf(x + x);
    return v - __fdividef(v + v, e + 1.0f);
}

__global__ void __launch_bounds__(256)
k_score(const float* __restrict__ keys, const float* __restrict__ Wloc,
        const float* __restrict__ vw, const float* __restrict__ vb,
        const void* __restrict__ mask) {
    __shared__ __align__(16) __nv_bfloat16 F_sh[128 * FP];    // 10.0 KB
    __shared__ __align__(16) __nv_bfloat16 W_sh[DIM_ * FP];   // 20.0 KB
    __shared__ float q_sh[DIM_], v_sh[DIM_];

    const int b = blockIdx.y, t0 = blockIdx.x * 128;
    const int tid = threadIdx.x, w = tid >> 5, lane = tid & 31;
    const int g = lane >> 2, tg = lane & 3;

    // stage Wloc -> bf16 [d][f] (row-major == col-major k16n8 B operand)
    for (int idx = tid; idx < DIM_ * NF_; idx += 256)
        W_sh[(idx >> 5) * FP + (idx & 31)] = __float2bfloat16(Wloc[idx]);
    q_sh[tid] = g_q[b * DIM_ + tid];
    v_sh[tid] = vw[tid];
    // stage F tile (128 x 32 bf16) as u32
    {
        const uint32_t* src = (const uint32_t*)(g_Fh + (size_t)(b * T_ + t0) * NF_);
        uint32_t* dstF = (uint32_t*)F_sh;
        for (int idx = tid; idx < 128 * 16; idx += 256) {
            int row = idx >> 4, col = idx & 15;
            dstF[row * (FP / 2) + col] = src[idx];
        }
    }
    const float vb0 = vb[0];
    __syncthreads();

    // A fragments (m16k16, 2 k-steps) for this warp's 16 t-rows
    const __nv_bfloat16* Fb = F_sh + (w * 16) * FP;
    uint32_t a[2][4];
#pragma unroll
    for (int ks = 0; ks < 2; ++ks) {
        const int f0 = ks * 16 + 2 * tg;
        a[ks][0] = *(const uint32_t*)(Fb + g * FP + f0);
        a[ks][1] = *(const uint32_t*)(Fb + (g + 8) * FP + f0);
        a[ks][2] = *(const uint32_t*)(Fb + g * FP + f0 + 8);
        a[ks][3] = *(const uint32_t*)(Fb + (g + 8) * FP + f0 + 8);
    }

    const size_t row0 = (size_t)(b * T_ + t0 + w * 16 + g) * DIM_;
    const size_t row8 = row0 + 8 * DIM_;
    float sc0 = 0.0f, sc1 = 0.0f;

#pragma unroll 2
    for (int nt = 0; nt < 32; ++nt) {
        const int n0 = nt * 8;
        const int d  = n0 + 2 * tg;
        const __nv_bfloat16* Wb = W_sh + (n0 + g) * FP + 2 * tg;
        const uint32_t b00 = *(const uint32_t*)(Wb);
        const uint32_t b01 = *(const uint32_t*)(Wb + 8);
        const uint32_t b10 = *(const uint32_t*)(Wb + 16);
        const uint32_t b11 = *(const uint32_t*)(Wb + 24);
        // prefetch keys + per-d constants while MMA runs
        const float2 k0 = *(const float2*)(keys + row0 + d);
        const float2 k1 = *(const float2*)(keys + row8 + d);
        const float2 q2 = *(const float2*)&q_sh[d];
        const float2 v2 = *(const float2*)&v_sh[d];

        float c0 = 0.f, c1 = 0.f, c2 = 0.f, c3 = 0.f;
        asm volatile(
            "mma.sync.aligned.m16n8k16.row.col.f32.bf16.bf16.f32 "
            "{%0,%1,%2,%3}, {%4,%5,%6,%7}, {%8,%9}, {%0,%1,%2,%3};"
            : "+f"(c0), "+f"(c1), "+f"(c2), "+f"(c3)
            : "r"(a[0][0]), "r"(a[0][1]), "r"(a[0][2]), "r"(a[0][3]),
              "r"(b00), "r"(b01));
        asm volatile(
            "mma.sync.aligned.m16n8k16.row.col.f32.bf16.bf16.f32 "
            "{%0,%1,%2,%3}, {%4,%5,%6,%7}, {%8,%9}, {%0,%1,%2,%3};"
            : "+f"(c0), "+f"(c1), "+f"(c2), "+f"(c3)
            : "r"(a[1][0]), "r"(a[1][1]), "r"(a[1][2]), "r"(a[1][3]),
              "r"(b10), "r"(b11));

        sc0 += score_term(c0, k0.x + q2.x, v2.x) + score_term(c1, k0.y + q2.y, v2.y);
        sc1 += score_term(c2, k1.x + q2.x, v2.x) + score_term(c3, k1.y + q2.y, v2.y);
    }

    // reduce over the 4 lanes sharing a t-row (each covered d%8 in {2tg,2tg+1})
    sc0 += __shfl_xor_sync(0xffffffffu, sc0, 1);
    sc0 += __shfl_xor_sync(0xffffffffu, sc0, 2);
    sc1 += __shfl_xor_sync(0xffffffffu, sc1, 1);
    sc1 += __shfl_xor_sync(0xffffffffu, sc1, 2);
    if (tg == 0) {
        const int isf = g_det[1], isu8 = g_det[0];
        const int t = t0 + w * 16 + g;
        float s0 = sc0 + vb0;
        float s1 = sc1 + vb0;
        if (mask_at(mask, b * T_ + t, isf, isu8))     s0 = NEG_;
        if (mask_at(mask, b * T_ + t + 8, isf, isu8)) s1 = NEG_;
        g_S[b * T_ + t]     = s0;
        g_S[b * T_ + t + 8] = s1;
    }
}

// ---------------- K4: softmax per row ----------------
__global__ void k_softmax(float* __restrict__ align_out) {
    const int b = blockIdx.x, tid = threadIdx.x;   // 512 threads
    __shared__ float sha[16], shb[16];
    float v[8];
    float mx = -3.4e38f;
#pragma unroll
    for (int i = 0; i < 8; ++i) {
        v[i] = g_S[b * T_ + tid + i * 512];
        mx = fmaxf(mx, v[i]);
    }
#pragma unroll
    for (int o = 16; o > 0; o >>= 1) mx = fmaxf(mx, __shfl_xor_sync(0xffffffffu, mx, o));
    if ((tid & 31) == 0) sha[tid >> 5] = mx;
    __syncthreads();
    if (tid < 32) {
        float t = (tid < 16) ? sha[tid] : -3.4e38f;
#pragma unroll
        for (int o = 8; o > 0; o >>= 1) t = fmaxf(t, __shfl_xor_sync(0xffffffffu, t, o));
        if (tid == 0) sha[0] = t;
    }
    __syncthreads();
    mx = sha[0];
    float sum = 0.0f;
#pragma unroll
    for (int i = 0; i < 8; ++i) { v[i] = __expf(v[i] - mx); sum += v[i]; }
#pragma unroll
    for (int o = 16; o > 0; o >>= 1) sum += __shfl_xor_sync(0xffffffffu, sum, o);
    if ((tid & 31) == 0) shb[tid >> 5] = sum;
    __syncthreads();
    if (tid < 32) {
        float t = (tid < 16) ? shb[tid] : 0.0f;
#pragma unroll
        for (int o = 8; o > 0; o >>= 1) t += __shfl_xor_sync(0xffffffffu, t, o);
        if (tid == 0) shb[0] = t;
    }
    __syncthreads();
    const float inv = 1.0f / shb[0];
#pragma unroll
    for (int i = 0; i < 8; ++i)
        align_out[b * T_ + tid + i * 512] = v[i] * inv;
}

// ---------------- K5: context partials (16 splits) + K6: reduce ----------------
__global__ void __launch_bounds__(256) k_context(const float* __restrict__ values,
                                                 const float* __restrict__ align) {
    __shared__ float al[256];
    const int b = blockIdx.y, sp = blockIdx.x, tid = threadIdx.x;
    const int tbase = sp * 256;
    al[tid] = align[b * T_ + tbase + tid];
    __syncthreads();
    const float* vp = values + ((size_t)(b * T_ + tbase)) * DIM_ + tid;
    float acc = 0.0f;
#pragma unroll 16
    for (int t = 0; t < 256; ++t)
        acc = fmaf(al[t], vp[(size_t)t * DIM_], acc);
    g_partial[(sp * B_ + b) * DIM_ + tid] = acc;
}

__global__ void k_reduce(float* __restrict__ att_out) {
    const int b = blockIdx.x, d = threadIdx.x;
    float s = 0.0f;
#pragma unroll
    for (int sp = 0; sp < NSPLIT; ++sp) s += g_partial[(sp * B_ + b) * DIM_ + d];
    att_out[b * DIM_ + d] = s;
}

// ---------------- launch ----------------
extern "C" void kernel_launch(void* const* d_in, const int* in_sizes, int n_in,
                              void* d_out, int out_size) {
    const float* query  = (const float*)d_in[0];
    const float* keys   = (const float*)d_in[1];
    const float* values = (const float*)d_in[2];
    const float* pa     = (const float*)d_in[3];
    const void*  mask   = d_in[4];
    const float* Wq     = (const float*)d_in[5];
    const float* cw     = (const float*)d_in[6];
    const float* Wloc   = (const float*)d_in[7];
    const float* vw     = (const float*)d_in[8];
    const float* vb     = (const float*)d_in[9];

    float* out = (float*)d_out;
    float *att_ptr, *align_ptr;
    if (out_size >= B_ * DIM_ + BT_) {
        att_ptr = out;
        align_ptr = out + B_ * DIM_;
    } else if (out_size == BT_) {
        float* p; cudaGetSymbolAddress((void**)&p, g_att_scratch);
        att_ptr = p; align_ptr = out;
    } else {
        float* p; cudaGetSymbolAddress((void**)&p, g_align_scratch);
        att_ptr = out; align_ptr = p;
    }

    k_reset<<<1, 1>>>();
    k_detect<<<64, 256>>>((const unsigned int*)mask);
    k_qproj<<<dim3(2, B_), 256>>>(query, Wq);
    k_conv<<<dim3(T_ / 128, B_), 256>>>(pa, cw);
    k_score<<<dim3(T_ / 128, B_), 256>>>(keys, Wloc, vw, vb, mask);
    k_softmax<<<B_, 512>>>(align_ptr);
    k_context<<<dim3(NSPLIT, B_), 256>>>(values, align_ptr);
    k_reduce<<<B_, DIM_>>>(att_ptr);
}

// round 14
// speedup vs baseline: 1.1332x; 1.0801x over previous
#include <cuda_runtime.h>
#include <cuda_bf16.h>
#include <cstdint>

#define B_   64
#define T_   4096
#define DIM_ 256
#define NF_  32
#define KS_  31
#define PAD_ 15
#define NEG_ (-1e30f)
#define BT_  (B_ * T_)
#define NSPLIT 16
#define CE    2.885390081777926815f   // 2*log2(e)

// ---------------- scratch (device globals; no allocations) ----------------
__device__ float g_q[B_ * DIM_];                     // 64 KB
__device__ float g_S[BT_];                           // raw masked scores
__device__ float g_partial[NSPLIT * B_ * DIM_];      // context partials
__device__ float g_align_scratch[BT_];
__device__ float g_att_scratch[B_ * DIM_];
__device__ int   g_det[2];

// ---------------- K0: mask dtype detection ----------------
__global__ void k_reset() { g_det[0] = 0; g_det[1] = 0; }

// sample first 65536 words (256KB == min possible mask buffer size)
__global__ void k_detect(const unsigned int* __restrict__ mw) {
    int i = (blockIdx.x * 256 + threadIdx.x) * 4;
#pragma unroll
    for (int j = 0; j < 4; ++j) {
        unsigned v = mw[i + j];
        if (v == 0x3f800000u)      atomicOr(&g_det[1], 1);   // float 1.0
        else if (v > 1u)           atomicOr(&g_det[0], 1);   // packed bytes
    }
}

__device__ __forceinline__ bool mask_at(const void* m, int idx, int isf, int isu8) {
    if (isf)  return ((const float*)m)[idx] != 0.0f;
    if (isu8) return ((const unsigned char*)m)[idx] != 0;
    return ((const int*)m)[idx] != 0;
}

// ---------------- K1: q = query @ Wq^T  (4-way interleaved, 128 blocks) ---
__global__ void __launch_bounds__(256) k_qproj(const float* __restrict__ query,
                                               const float* __restrict__ Wq) {
    __shared__ float qs[DIM_];
    const int b = blockIdx.y, half = blockIdx.x;
    const int tid = threadIdx.x, w = tid >> 5, lane = tid & 31;
    qs[tid] = query[b * DIM_ + tid];
    __syncthreads();
    const int dbase = half * 128 + w * 16;
#pragma unroll
    for (int it = 0; it < 4; ++it) {
        const int d0 = dbase + it * 4;
        float a0 = 0.f, a1 = 0.f, a2 = 0.f, a3 = 0.f;
        const float* r0 = Wq + (size_t)(d0 + 0) * DIM_;
        const float* r1 = Wq + (size_t)(d0 + 1) * DIM_;
        const float* r2 = Wq + (size_t)(d0 + 2) * DIM_;
        const float* r3 = Wq + (size_t)(d0 + 3) * DIM_;
#pragma unroll
        for (int e = 0; e < 8; ++e) {
            const int c = lane + 32 * e;
            const float q = qs[c];
            a0 = fmaf(r0[c], q, a0);
            a1 = fmaf(r1[c], q, a1);
            a2 = fmaf(r2[c], q, a2);
            a3 = fmaf(r3[c], q, a3);
        }
#pragma unroll
        for (int o = 16; o > 0; o >>= 1) {
            a0 += __shfl_xor_sync(0xffffffffu, a0, o);
            a1 += __shfl_xor_sync(0xffffffffu, a1, o);
            a2 += __shfl_xor_sync(0xffffffffu, a2, o);
            a3 += __shfl_xor_sync(0xffffffffu, a3, o);
        }
        if (lane == 0)
            *(float4*)&g_q[b * DIM_ + d0] = make_float4(a0, a1, a2, a3);
    }
}

// ---------------- K3: fused conv + score kernel ----------------
#define FP 40   // bf16 smem pitch: conflict-free v1/v2 fragment loads

__global__ void __launch_bounds__(256)
k_score(const float* __restrict__ keys, const float* __restrict__ Wloc,
        const float* __restrict__ vw, const float* __restrict__ vb,
        const void* __restrict__ mask,
        const float* __restrict__ pa, const float* __restrict__ cw) {
    __shared__ __align__(16) __nv_bfloat16 F_sh[128 * FP];    // 10.0 KB
    __shared__ __align__(16) __nv_bfloat16 W_sh[DIM_ * FP];   // 20.0 KB
    __shared__ float qC_sh[DIM_], vm_sh[DIM_];                 // q*CE, -2*v
    __shared__ float pa_sh[160];
    __shared__ float cw_sh[NF_ * KS_];
    __shared__ float sh_V;                                     // sum of v_w

    const int b = blockIdx.y, t0 = blockIdx.x * 128;
    const int tid = threadIdx.x, w = tid >> 5, lane = tid & 31;
    const int g = lane >> 2, tg = lane & 3;

    // ---- stage everything (one block sync total) ----
    for (int idx = tid; idx < DIM_ * NF_; idx += 256)
        W_sh[(idx >> 5) * FP + (idx & 31)] = __float2bfloat16(Wloc[idx]);
    qC_sh[tid] = g_q[b * DIM_ + tid] * CE;
    const float vme = vw[tid];
    vm_sh[tid] = -2.0f * vme;
    for (int i = tid; i < 160; i += 256) {
        int t = t0 + i - PAD_;
        pa_sh[i] = (t >= 0 && t < T_) ? pa[b * T_ + t] : 0.0f;
    }
    for (int i = tid; i < NF_ * KS_; i += 256) cw_sh[i] = cw[i];
    const float vb0 = vb[0];
    __syncthreads();

    // ---- V = sum(v_w) (warp 0), overlapped with conv below ----
    if (w == 0) {
        float s = 0.0f;
#pragma unroll
        for (int e = 0; e < 8; ++e) s += vm_sh[lane + 32 * e];
#pragma unroll
        for (int o = 16; o > 0; o >>= 1) s += __shfl_xor_sync(0xffffffffu, s, o);
        if (lane == 0) sh_V = -0.5f * s;
    }

    // ---- conv for this warp's own 16 t-rows (lane = filter) ----
    {
        float cr[KS_];
#pragma unroll
        for (int k = 0; k < KS_; ++k) cr[k] = cw_sh[lane * KS_ + k];  // stride-31: conflict-free
        float wv[KS_];
#pragma unroll
        for (int k = 0; k < KS_; ++k) wv[k] = pa_sh[w * 16 + k];      // broadcast
        uint32_t* Frow = (uint32_t*)(F_sh + (w * 16) * FP);
#pragma unroll
        for (int i = 0; i < 16; ++i) {
            float a = 0.0f;
#pragma unroll
            for (int k = 0; k < KS_; ++k) a = fmaf(wv[k], cr[k], a);
            unsigned short us = __bfloat16_as_ushort(__float2bfloat16(a));
            unsigned nxt = __shfl_down_sync(0xffffffffu, (unsigned)us, 1);
            if (!(lane & 1))  // 16 lanes, stride-2 words: conflict-free STS.32
                Frow[i * (FP / 2) + (lane >> 1)] = (unsigned)us | (nxt << 16);
#pragma unroll
            for (int k = 0; k < KS_ - 1; ++k) wv[k] = wv[k + 1];
            wv[KS_ - 1] = pa_sh[w * 16 + i + KS_];                    // max 158 < 160
        }
    }
    __syncwarp();   // F_sh rows produced and consumed by the same warp

    // ---- A fragments (m16k16, 2 k-steps) for this warp's 16 t-rows ----
    const __nv_bfloat16* Fb = F_sh + (w * 16) * FP;
    uint32_t a[2][4];
#pragma unroll
    for (int ks = 0; ks < 2; ++ks) {
        const int f0 = ks * 16 + 2 * tg;
        a[ks][0] = *(const uint32_t*)(Fb + g * FP + f0);
        a[ks][1] = *(const uint32_t*)(Fb + (g + 8) * FP + f0);
        a[ks][2] = *(const uint32_t*)(Fb + g * FP + f0 + 8);
        a[ks][3] = *(const uint32_t*)(Fb + (g + 8) * FP + f0 + 8);
    }

    const size_t row0 = (size_t)(b * T_ + t0 + w * 16 + g) * DIM_;
    const size_t row8 = row0 + 8 * DIM_;
    float sc0 = 0.0f, sc1 = 0.0f;

#pragma unroll 2
    for (int nt = 0; nt < 32; ++nt) {
        const int n0 = nt * 8;
        const int d  = n0 + 2 * tg;
        const __nv_bfloat16* Wb = W_sh + (n0 + g) * FP + 2 * tg;
        const uint32_t b00 = *(const uint32_t*)(Wb);
        const uint32_t b01 = *(const uint32_t*)(Wb + 8);
        const uint32_t b10 = *(const uint32_t*)(Wb + 16);
        const uint32_t b11 = *(const uint32_t*)(Wb + 24);
        // prefetch keys + per-d constants while MMA runs
        const float2 k0 = *(const float2*)(keys + row0 + d);
        const float2 k1 = *(const float2*)(keys + row8 + d);
        const float2 q2 = *(const float2*)&qC_sh[d];
        const float2 v2 = *(const float2*)&vm_sh[d];

        float c0 = 0.f, c1 = 0.f, c2 = 0.f, c3 = 0.f;
        asm volatile(
            "mma.sync.aligned.m16n8k16.row.col.f32.bf16.bf16.f32 "
            "{%0,%1,%2,%3}, {%4,%5,%6,%7}, {%8,%9}, {%0,%1,%2,%3};"
            : "+f"(c0), "+f"(c1), "+f"(c2), "+f"(c3)
            : "r"(a[0][0]), "r"(a[0][1]), "r"(a[0][2]), "r"(a[0][3]),
              "r"(b00), "r"(b01));
        asm volatile(
            "mma.sync.aligned.m16n8k16.row.col.f32.bf16.bf16.f32 "
            "{%0,%1,%2,%3}, {%4,%5,%6,%7}, {%8,%9}, {%0,%1,%2,%3};"
            : "+f"(c0), "+f"(c1), "+f"(c2), "+f"(c3)
            : "r"(a[1][0]), "r"(a[1][1]), "r"(a[1][2]), "r"(a[1][3]),
              "r"(b10), "r"(b11));

        // v*tanh(x) = v - 2v*rcp(ex2(x*CE)+1);  vm = -2v, V added at end
        const float kC0x = fmaf(k0.x, CE, q2.x);
        const float kC0y = fmaf(k0.y, CE, q2.y);
        const float kC1x = fmaf(k1.x, CE, q2.x);
        const float kC1y = fmaf(k1.y, CE, q2.y);
        float e0, e1, e2, e3, r0, r1, r2, r3;
        asm("ex2.approx.f32 %0, %1;" : "=f"(e0) : "f"(fmaf(c0, CE, kC0x)));
        asm("ex2.approx.f32 %0, %1;" : "=f"(e1) : "f"(fmaf(c1, CE, kC0y)));
        asm("ex2.approx.f32 %0, %1;" : "=f"(e2) : "f"(fmaf(c2, CE, kC1x)));
        asm("ex2.approx.f32 %0, %1;" : "=f"(e3) : "f"(fmaf(c3, CE, kC1y)));
        asm("rcp.approx.f32 %0, %1;" : "=f"(r0) : "f"(e0 + 1.0f));
        asm("rcp.approx.f32 %0, %1;" : "=f"(r1) : "f"(e1 + 1.0f));
        asm("rcp.approx.f32 %0, %1;" : "=f"(r2) : "f"(e2 + 1.0f));
        asm("rcp.approx.f32 %0, %1;" : "=f"(r3) : "f"(e3 + 1.0f));
        sc0 = fmaf(v2.x, r0, sc0);
        sc0 = fmaf(v2.y, r1, sc0);
        sc1 = fmaf(v2.x, r2, sc1);
        sc1 = fmaf(v2.y, r3, sc1);
    }

    // reduce over the 4 lanes sharing a t-row
    sc0 += __shfl_xor_sync(0xffffffffu, sc0, 1);
    sc0 += __shfl_xor_sync(0xffffffffu, sc0, 2);
    sc1 += __shfl_xor_sync(0xffffffffu, sc1, 1);
    sc1 += __shfl_xor_sync(0xffffffffu, sc1, 2);
    if (tg == 0) {
        const int isf = g_det[1], isu8 = g_det[0];
        const float base = sh_V + vb0;
        const int t = t0 + w * 16 + g;
        float s0 = sc0 + base;
        float s1 = sc1 + base;
        if (mask_at(mask, b * T_ + t, isf, isu8))     s0 = NEG_;
        if (mask_at(mask, b * T_ + t + 8, isf, isu8)) s1 = NEG_;
        g_S[b * T_ + t]     = s0;
        g_S[b * T_ + t + 8] = s1;
    }
}

// ---------------- K4: softmax per row ----------------
__global__ void k_softmax(float* __restrict__ align_out) {
    const int b = blockIdx.x, tid = threadIdx.x;   // 512 threads
    __shared__ float sha[16], shb[16];
    float v[8];
    float mx = -3.4e38f;
#pragma unroll
    for (int i = 0; i < 8; ++i) {
        v[i] = g_S[b * T_ + tid + i * 512];
        mx = fmaxf(mx, v[i]);
    }
#pragma unroll
    for (int o = 16; o > 0; o >>= 1) mx = fmaxf(mx, __shfl_xor_sync(0xffffffffu, mx, o));
    if ((tid & 31) == 0) sha[tid >> 5] = mx;
    __syncthreads();
    if (tid < 32) {
        float t = (tid < 16) ? sha[tid] : -3.4e38f;
#pragma unroll
        for (int o = 8; o > 0; o >>= 1) t = fmaxf(t, __shfl_xor_sync(0xffffffffu, t, o));
        if (tid == 0) sha[0] = t;
    }
    __syncthreads();
    mx = sha[0];
    float sum = 0.0f;
#pragma unroll
    for (int i = 0; i < 8; ++i) { v[i] = __expf(v[i] - mx); sum += v[i]; }
#pragma unroll
    for (int o = 16; o > 0; o >>= 1) sum += __shfl_xor_sync(0xffffffffu, sum, o);
    if ((tid & 31) == 0) shb[tid >> 5] = sum;
    __syncthreads();
    if (tid < 32) {
        float t = (tid < 16) ? shb[tid] : 0.0f;
#pragma unroll
        for (int o = 8; o > 0; o >>= 1) t += __shfl_xor_sync(0xffffffffu, t, o);
        if (tid == 0) shb[0] = t;
    }
    __syncthreads();
    const float inv = 1.0f / shb[0];
#pragma unroll
    for (int i = 0; i < 8; ++i)
        align_out[b * T_ + tid + i * 512] = v[i] * inv;
}

// ---------------- K5: context partials (16 splits) + K6: reduce ----------------
__global__ void __launch_bounds__(256) k_context(const float* __restrict__ values,
                                                 const float* __restrict__ align) {
    __shared__ float al[256];
    const int b = blockIdx.y, sp = blockIdx.x, tid = threadIdx.x;
    const int tbase = sp * 256;
    al[tid] = align[b * T_ + tbase + tid];
    __syncthreads();
    const float* vp = values + ((size_t)(b * T_ + tbase)) * DIM_ + tid;
    float acc = 0.0f;
#pragma unroll 16
    for (int t = 0; t < 256; ++t)
        acc = fmaf(al[t], vp[(size_t)t * DIM_], acc);
    g_partial[(sp * B_ + b) * DIM_ + tid] = acc;
}

__global__ void k_reduce(float* __restrict__ att_out) {
    const int b = blockIdx.x, d = threadIdx.x;
    float s = 0.0f;
#pragma unroll
    for (int sp = 0; sp < NSPLIT; ++sp) s += g_partial[(sp * B_ + b) * DIM_ + d];
    att_out[b * DIM_ + d] = s;
}

// ---------------- launch ----------------
extern "C" void kernel_launch(void* const* d_in, const int* in_sizes, int n_in,
                              void* d_out, int out_size) {
    const float* query  = (const float*)d_in[0];
    const float* keys   = (const float*)d_in[1];
    const float* values = (const float*)d_in[2];
    const float* pa     = (const float*)d_in[3];
    const void*  mask   = d_in[4];
    const float* Wq     = (const float*)d_in[5];
    const float* cw     = (const float*)d_in[6];
    const float* Wloc   = (const float*)d_in[7];
    const float* vw     = (const float*)d_in[8];
    const float* vb     = (const float*)d_in[9];

    float* out = (float*)d_out;
    float *att_ptr, *align_ptr;
    if (out_size >= B_ * DIM_ + BT_) {
        att_ptr = out;
        align_ptr = out + B_ * DIM_;
    } else if (out_size == BT_) {
        float* p; cudaGetSymbolAddress((void**)&p, g_att_scratch);
        att_ptr = p; align_ptr = out;
    } else {
        float* p; cudaGetSymbolAddress((void**)&p, g_align_scratch);
        att_ptr = out; align_ptr = p;
    }

    k_reset<<<1, 1>>>();
    k_detect<<<64, 256>>>((const unsigned int*)mask);
    k_qproj<<<dim3(2, B_), 256>>>(query, Wq);
    k_score<<<dim3(T_ / 128, B_), 256>>>(keys, Wloc, vw, vb, mask, pa, cw);
    k_softmax<<<B_, 512>>>(align_ptr);
    k_context<<<dim3(NSPLIT, B_), 256>>>(values, align_ptr);
    k_reduce<<<B_, DIM_>>>(att_ptr);
}